// round 9
// baseline (speedup 1.0000x reference)
#include <cuda_runtime.h>
#include <math.h>
#include <stdint.h>

#define N_NODES 20000
#define E_EDGES 60000
#define F_INPUT 16
#define HDIM 64
#define L_LAYERS 3
#define G_GRAPHS 64
#define EPSV 1e-5f
#define KD 33              /* 32 edge-hidden + 1 bias slot */
#define JW (KD*HDIM)       /* 2112 columns */
#define BM 16              /* node rows per CTA in main kernel */
#define MAIN_THREADS 544   /* 17 warps; threads 0..527 own 4 cols each */
#define GEMM_THREADS 528   /* 528*4 = 2112 */
#define NWARPS (MAIN_THREADS/32)

// ---------------- device scratch (static, allocation-free; self-cleaning) ----------------
__device__ float g_h[N_NODES*HDIM];
__device__ float g_out[N_NODES*HDIM];
__device__ float g_agg[N_NODES*HDIM];        // zero at load; k_post re-zeroes after read
__device__ float g_W2p[L_LAYERS*HDIM*JW + 2*JW];  // +2*JW pad for depth-2 prefetch overread
__device__ int   g_deg_col[N_NODES];         // zero at load; k_setup re-zeroes after read
__device__ float g_inv_deg[N_NODES];
__device__ int   g_deg_row[N_NODES];         // zero at load; k_scan re-zeroes after read
__device__ int   g_row_ptr[N_NODES+1];
__device__ int   g_cursor[N_NODES];
__device__ int   g_se_row[E_EDGES];
__device__ int   g_se_col[E_EDGES];
__device__ float g_musum[HDIM];              // zeroed by k_bnstats after read
__device__ float g_sqsum[HDIM];
__device__ float g_mu[HDIM];
__device__ float g_scale[HDIM];
__device__ float g_gsum[G_GRAPHS*HDIM];      // zeroed by k_cls after read
__device__ unsigned int g_gmaxe[G_GRAPHS*HDIM];
__device__ int   g_gcnt[G_GRAPHS];

// monotone float<->uint encoding for atomicMax on floats; 0u is below all encodings
__device__ __forceinline__ unsigned int fenc(float f){
    int i = __float_as_int(f);
    return (i >= 0) ? ((unsigned int)i | 0x80000000u) : (unsigned int)(~i);
}
__device__ __forceinline__ float fdec(unsigned int u){
    int i = (u & 0x80000000u) ? (int)(u & 0x7FFFFFFFu) : ~(int)u;
    return __int_as_float(i);
}

// ---------------- setup kernels ----------------
__global__ void k_deg(const int* __restrict__ ei){
    int i = blockIdx.x*blockDim.x + threadIdx.x;
    if (i >= E_EDGES) return;
    atomicAdd(&g_deg_row[ei[i]], 1);
    atomicAdd(&g_deg_col[ei[E_EDGES + i]], 1);
}

// single-block warp-shuffle scan over g_deg_row -> g_row_ptr / g_cursor (zeroes deg_row)
__global__ void k_scan(){
    __shared__ int wsum[32];
    __shared__ int s_carry;
    int tid = threadIdx.x, lane = tid & 31, wid = tid >> 5;
    if (tid == 0) s_carry = 0;
    __syncthreads();
    for (int base = 0; base < N_NODES; base += 1024){
        int idx = base + tid;
        int v = 0;
        if (idx < N_NODES){ v = g_deg_row[idx]; g_deg_row[idx] = 0; }
        int inc = v;
        #pragma unroll
        for (int off = 1; off < 32; off <<= 1){
            int t = __shfl_up_sync(0xffffffffu, inc, off);
            if (lane >= off) inc += t;
        }
        if (lane == 31) wsum[wid] = inc;
        __syncthreads();
        if (wid == 0){
            int s = wsum[lane];
            #pragma unroll
            for (int off = 1; off < 32; off <<= 1){
                int t = __shfl_up_sync(0xffffffffu, s, off);
                if (lane >= off) s += t;
            }
            wsum[lane] = s;
        }
        __syncthreads();
        int woff = (wid > 0) ? wsum[wid-1] : 0;
        int excl = s_carry + woff + inc - v;
        if (idx < N_NODES){ g_row_ptr[idx] = excl; g_cursor[idx] = excl; }
        int tot = wsum[31];
        __syncthreads();
        if (tid == 0) s_carry += tot;
        __syncthreads();
    }
    if (tid == 0) g_row_ptr[N_NODES] = s_carry;
}

// fused: fill CSR + permute W2||b2 + inv_deg(+zero deg_col) + embedding GEMM
#define SB_FILL 235
#define SB_PERM 1584
#define SB_INV  79
#define SB_EMB  5000
#define SB_TOTAL (SB_FILL + SB_PERM + SB_INV + SB_EMB)
__global__ void k_setup(const int* __restrict__ ei,
                        const float* __restrict__ eW2, const float* __restrict__ eb2,
                        const float* __restrict__ x, const float* __restrict__ embW,
                        const float* __restrict__ embB){
    int b = blockIdx.x;
    int tid = threadIdx.x;
    if (b < SB_FILL){
        int i = b*256 + tid;
        if (i < E_EDGES){
            int r = ei[i], c = ei[E_EDGES + i];
            int p = atomicAdd(&g_cursor[r], 1);
            g_se_row[p] = r;
            g_se_col[p] = c;
        }
        return;
    }
    b -= SB_FILL;
    if (b < SB_PERM){
        int idx = b*256 + tid;                 // < L*H*JW = 405504 exactly
        int l = idx / (HDIM*JW);
        int rem = idx - l*(HDIM*JW);
        int i = rem / JW;
        int j = rem - i*JW;
        int k = j >> 6, o = j & 63;
        float v;
        if (k < 32) v = eW2[((size_t)(l*32 + k))*4096 + i*64 + o];
        else        v = eb2[(size_t)l*4096 + i*64 + o];
        g_W2p[idx] = v;
        return;
    }
    b -= SB_PERM;
    if (b < SB_INV){
        int i = b*256 + tid;
        if (i < N_NODES){
            int d = g_deg_col[i];
            g_deg_col[i] = 0;                  // ready for next replay
            g_inv_deg[i] = (d > 0) ? (1.0f/(float)d) : 0.0f;
        }
        return;
    }
    b -= SB_INV;
    {   // embedding: 4 nodes per block
        __shared__ float xs[4*F_INPUT];
        int nb = b*4;
        if (tid < 4*F_INPUT) xs[tid] = x[nb*F_INPUT + tid];
        __syncthreads();
        int r = tid >> 6, o = tid & 63;
        float acc = embB[o];
        #pragma unroll
        for (int i = 0; i < F_INPUT; i++)
            acc = fmaf(xs[r*F_INPUT + i], embW[i*HDIM + o], acc);
        g_h[(nb + r)*HDIM + o] = acc;
    }
}

// ---------------- main fused kernel: C-tile GEMM (f32x2, 17 warps, 4 cols/thr) + edge scatter ----------------
__global__ void __launch_bounds__(MAIN_THREADS, 1)
k_main(int l, const float* __restrict__ W1, const float* __restrict__ b1){
    extern __shared__ float sm[];
    float* Cs  = sm;                 // [BM][JW]
    float* hsT = sm + BM*JW;         // [HDIM][BM] transposed h tile
    __shared__ float w1s[32], b1s[32];

    int tid = threadIdx.x;
    int n0  = blockIdx.x * BM;

    if (tid < 32){ w1s[tid] = W1[l*32 + tid]; b1s[tid] = b1[l*32 + tid]; }
    for (int idx = tid; idx < BM*HDIM; idx += MAIN_THREADS){
        int r = idx >> 6, i = idx & 63;
        hsT[i*BM + r] = g_h[(n0 + r)*HDIM + i];
    }
    __syncthreads();

    // GEMM: C[r][j] = sum_i h[r,i]*W2p[i,j]; thread t<528 owns cols 4t..4t+3.
    // 1 LDG.128 (W, depth-2 buffered) + 4 LDS.128 (h row) + 32 FMA2 per i.
    if (tid < GEMM_THREADS){
        const float4* __restrict__ Wp4 =
            reinterpret_cast<const float4*>(g_W2p + (size_t)l*HDIM*JW) + tid;
        unsigned long long acc[4][8];
        #pragma unroll
        for (int c = 0; c < 4; c++)
            #pragma unroll
            for (int rp = 0; rp < 8; rp++) acc[c][rp] = 0ull;

        float4 wbuf[2];
        wbuf[0] = Wp4[0];
        wbuf[1] = Wp4[JW/4];
        const float4* Wpre = Wp4 + 2*(JW/4);        // points at row i+2
        const float* hs = hsT;

        #pragma unroll 2
        for (int i = 0; i < HDIM; i++){
            float4 wn = *Wpre; Wpre += (JW/4);      // prefetch row i+2 (pad covers tail)

            ulonglong2 q0 = *reinterpret_cast<const ulonglong2*>(hs);
            ulonglong2 q1 = *reinterpret_cast<const ulonglong2*>(hs + 4);
            ulonglong2 q2 = *reinterpret_cast<const ulonglong2*>(hs + 8);
            ulonglong2 q3 = *reinterpret_cast<const ulonglong2*>(hs + 12);
            hs += BM;

            float4 wv = wbuf[i & 1];
            unsigned long long w2x, w2y, w2z, w2w;
            asm("mov.b64 %0, {%1, %1};" : "=l"(w2x) : "f"(wv.x));
            asm("mov.b64 %0, {%1, %1};" : "=l"(w2y) : "f"(wv.y));
            asm("mov.b64 %0, {%1, %1};" : "=l"(w2z) : "f"(wv.z));
            asm("mov.b64 %0, {%1, %1};" : "=l"(w2w) : "f"(wv.w));

            unsigned long long hp0 = q0.x, hp1 = q0.y, hp2 = q1.x, hp3 = q1.y;
            unsigned long long hp4 = q2.x, hp5 = q2.y, hp6 = q3.x, hp7 = q3.y;

            #define FMA2_ROW(c, w2) \
                asm("fma.rn.f32x2 %0, %1, %2, %0;" : "+l"(acc[c][0]) : "l"(hp0), "l"(w2)); \
                asm("fma.rn.f32x2 %0, %1, %2, %0;" : "+l"(acc[c][1]) : "l"(hp1), "l"(w2)); \
                asm("fma.rn.f32x2 %0, %1, %2, %0;" : "+l"(acc[c][2]) : "l"(hp2), "l"(w2)); \
                asm("fma.rn.f32x2 %0, %1, %2, %0;" : "+l"(acc[c][3]) : "l"(hp3), "l"(w2)); \
                asm("fma.rn.f32x2 %0, %1, %2, %0;" : "+l"(acc[c][4]) : "l"(hp4), "l"(w2)); \
                asm("fma.rn.f32x2 %0, %1, %2, %0;" : "+l"(acc[c][5]) : "l"(hp5), "l"(w2)); \
                asm("fma.rn.f32x2 %0, %1, %2, %0;" : "+l"(acc[c][6]) : "l"(hp6), "l"(w2)); \
                asm("fma.rn.f32x2 %0, %1, %2, %0;" : "+l"(acc[c][7]) : "l"(hp7), "l"(w2));
            FMA2_ROW(0, w2x)
            FMA2_ROW(1, w2y)
            FMA2_ROW(2, w2z)
            FMA2_ROW(3, w2w)
            #undef FMA2_ROW

            wbuf[i & 1] = wn;
        }

        // store C tile: per row pair, two STS.128
        #pragma unroll
        for (int rp = 0; rp < 8; rp++){
            float lo[4], hi[4];
            #pragma unroll
            for (int c = 0; c < 4; c++)
                asm("mov.b64 {%0, %1}, %2;" : "=f"(lo[c]), "=f"(hi[c]) : "l"(acc[c][rp]));
            *reinterpret_cast<float4*>(&Cs[(2*rp  )*JW + 4*tid]) =
                make_float4(lo[0], lo[1], lo[2], lo[3]);
            *reinterpret_cast<float4*>(&Cs[(2*rp+1)*JW + 4*tid]) =
                make_float4(hi[0], hi[1], hi[2], hi[3]);
        }
    }
    __syncthreads();

    // epilogue: per edge, distance + hid + msg = hid_ext . C[row], scatter to agg[col]
    int wid = tid >> 5, lane = tid & 31;
    int es = g_row_ptr[n0], ee = g_row_ptr[n0 + BM];
    for (int e = es + wid; e < ee; e += NWARPS){
        int r = g_se_row[e] - n0;
        int c = g_se_col[e];
        float dx = hsT[0*BM + r] - __ldg(&g_h[c*HDIM + 0]);
        float dy = hsT[1*BM + r] - __ldg(&g_h[c*HDIM + 1]);
        float dz = hsT[2*BM + r] - __ldg(&g_h[c*HDIM + 2]);
        float dd = sqrtf(dx*dx + dy*dy + dz*dz);
        const float* Cr = Cs + r*JW;
        float m0 = Cr[32*64 + lane];        // bias slot (hid=1)
        float m1 = Cr[32*64 + 32 + lane];
        #pragma unroll
        for (int k = 0; k < 32; k++){
            float hk = fmaxf(fmaf(dd, w1s[k], b1s[k]), 0.f);
            m0 = fmaf(hk, Cr[k*64 + lane],      m0);
            m1 = fmaf(hk, Cr[k*64 + 32 + lane], m1);
        }
        atomicAdd(&g_agg[c*HDIM + lane],      m0);
        atomicAdd(&g_agg[c*HDIM + 32 + lane], m1);
    }
}

// out = agg*inv_deg + h@self_W + self_b ; zero agg; fp32 BN stat atomics
__global__ void k_post(int l, const float* __restrict__ sW, const float* __restrict__ sb){
    __shared__ float hsm[4*HDIM];
    __shared__ float red[256];
    __shared__ float red2[256];
    int tid = threadIdx.x;
    int nb = blockIdx.x*4;
    hsm[tid] = g_h[nb*HDIM + tid];
    __syncthreads();
    int r = tid >> 6, o = tid & 63;
    int n = nb + r;
    float a = g_agg[n*HDIM + o];
    g_agg[n*HDIM + o] = 0.f;                 // ready for next layer / next replay
    float acc = a*g_inv_deg[n] + sb[l*HDIM + o];
    const float* W = sW + (size_t)l*HDIM*HDIM;
    #pragma unroll 16
    for (int i = 0; i < HDIM; i++)
        acc = fmaf(hsm[r*HDIM + i], W[i*HDIM + o], acc);
    g_out[n*HDIM + o] = acc;
    red[tid] = acc; red2[tid] = acc*acc;
    __syncthreads();
    if (tid < 64){
        float s  = red [tid] + red [tid+64] + red [tid+128] + red [tid+192];
        float s2 = red2[tid] + red2[tid+64] + red2[tid+128] + red2[tid+192];
        atomicAdd(&g_musum[tid], s);
        atomicAdd(&g_sqsum[tid], s2);
    }
}

__global__ void k_bnstats(int l, const float* __restrict__ gamma){
    int o = threadIdx.x;
    if (o >= HDIM) return;
    float mu  = g_musum[o] * (1.0f/(float)N_NODES);
    float ex2 = g_sqsum[o] * (1.0f/(float)N_NODES);
    float var = ex2 - mu*mu;
    g_mu[o] = mu;
    g_scale[o] = gamma[l*HDIM + o] * rsqrtf(var + EPSV);
    g_musum[o] = 0.f;                        // ready for next layer
    g_sqsum[o] = 0.f;
}

// BN apply + relu + skip; for last layer also graph pooling atomics
__global__ void k_bnapply(int l, const float* __restrict__ beta,
                          const int* __restrict__ batch, int do_pool){
    int idx = blockIdx.x*blockDim.x + threadIdx.x;
    if (idx >= N_NODES*HDIM) return;
    int o = idx & 63;
    float v = (g_out[idx] - g_mu[o])*g_scale[o] + beta[l*HDIM + o];
    float hnew = g_h[idx] + fmaxf(v, 0.f);
    g_h[idx] = hnew;
    if (do_pool){
        int n = idx >> 6;
        int g = batch[n];
        atomicAdd(&g_gsum[g*HDIM + o], hnew);
        atomicMax(&g_gmaxe[g*HDIM + o], fenc(hnew));
        if (o == 0) atomicAdd(&g_gcnt[g], 1);
    }
}

// ---------------- classifier (also zeroes pooling scratch after read) ----------------
__global__ void k_cls(const float* __restrict__ W1, const float* __restrict__ b1,
                      const float* __restrict__ W2, const float* __restrict__ b2,
                      float* __restrict__ out){
    __shared__ float gv[2*HDIM];
    __shared__ float h1[HDIM];
    __shared__ float partials[2];
    int g = blockIdx.x, tid = threadIdx.x;
    int cnt = g_gcnt[g];
    if (tid < HDIM){
        gv[tid] = g_gsum[g*HDIM + tid] / fmaxf((float)cnt, 1.f);
    } else {
        int o = tid - HDIM;
        gv[tid] = (cnt > 0) ? fdec(g_gmaxe[g*HDIM + o]) : 0.f;
    }
    __syncthreads();
    // scratch fully read -> zero for next replay
    if (tid < HDIM) g_gsum[g*HDIM + tid] = 0.f;
    else            g_gmaxe[g*HDIM + (tid - HDIM)] = 0u;
    if (tid == 0)   g_gcnt[g] = 0;
    if (tid < HDIM){
        float a = b1[tid];
        #pragma unroll 8
        for (int i = 0; i < 2*HDIM; i++)
            a = fmaf(gv[i], W1[i*HDIM + tid], a);
        h1[tid] = fmaxf(a, 0.f);
    }
    __syncthreads();
    float p = 0.f;
    if (tid < HDIM){
        p = h1[tid]*W2[tid];
        #pragma unroll
        for (int off = 16; off > 0; off >>= 1)
            p += __shfl_down_sync(0xffffffffu, p, off);
        if ((tid & 31) == 0) partials[tid >> 5] = p;
    }
    __syncthreads();
    if (tid == 0){
        float t = partials[0] + partials[1] + b2[0];
        out[g] = 1.f/(1.f + expf(-t));
    }
}

// ---------------- launcher ----------------
extern "C" void kernel_launch(void* const* d_in, const int* in_sizes, int n_in,
                              void* d_out, int out_size){
    const float* x        = (const float*)d_in[0];
    const int*   ei       = (const int*)  d_in[1];
    const int*   batch    = (const int*)  d_in[2];
    const float* emb_W    = (const float*)d_in[3];
    const float* emb_b    = (const float*)d_in[4];
    const float* edge_W1  = (const float*)d_in[5];
    const float* edge_b1  = (const float*)d_in[6];
    const float* edge_W2  = (const float*)d_in[7];
    const float* edge_b2  = (const float*)d_in[8];
    const float* self_W   = (const float*)d_in[9];
    const float* self_b   = (const float*)d_in[10];
    const float* bn_gamma = (const float*)d_in[11];
    const float* bn_beta  = (const float*)d_in[12];
    const float* cls_W1   = (const float*)d_in[13];
    const float* cls_b1   = (const float*)d_in[14];
    const float* cls_W2   = (const float*)d_in[15];
    const float* cls_b2   = (const float*)d_in[16];
    float* out = (float*)d_out;

    const int smem_main = (BM*JW + HDIM*BM)*(int)sizeof(float); // 139264 B
    cudaFuncSetAttribute(k_main, cudaFuncAttributeMaxDynamicSharedMemorySize, smem_main);

    const int TB = 256;
    const int gE   = (E_EDGES + TB - 1)/TB;          // 235
    const int gNH  = (N_NODES*HDIM + TB - 1)/TB;     // 5000
    const int gMain= N_NODES/BM;                     // 1250

    k_deg<<<gE, TB>>>(ei);
    k_scan<<<1, 1024>>>();
    k_setup<<<SB_TOTAL, TB>>>(ei, edge_W2, edge_b2, x, emb_W, emb_b);

    for (int l = 0; l < L_LAYERS; l++){
        k_main<<<gMain, MAIN_THREADS, smem_main>>>(l, edge_W1, edge_b1);
        k_post<<<N_NODES/4, TB>>>(l, self_W, self_b);
        k_bnstats<<<1, 64>>>(l, bn_gamma);
        k_bnapply<<<gNH, TB>>>(l, bn_beta, batch, (l == L_LAYERS-1) ? 1 : 0);
    }

    k_cls<<<G_GRAPHS, 128>>>(cls_W1, cls_b1, cls_W2, cls_b2, out);
}

// round 12
// speedup vs baseline: 1.2323x; 1.2323x over previous
#include <cuda_runtime.h>
#include <math.h>
#include <stdint.h>

#define N_NODES 20000
#define E_EDGES 60000
#define F_INPUT 16
#define HDIM 64
#define L_LAYERS 3
#define G_GRAPHS 64
#define EPSV 1e-5f
#define KD 33              /* 32 edge-hidden + 1 bias slot */
#define JW (KD*HDIM)       /* 2112 columns */
#define BM 16              /* node rows per CTA in main kernel */
#define MAIN_THREADS 352   /* 11 warps; 352*6 = 2112 columns */
#define NWARPS (MAIN_THREADS/32)

// ---------------- device scratch (static, allocation-free; self-cleaning) ----------------
__device__ float g_h[N_NODES*HDIM];
__device__ float g_out[N_NODES*HDIM];
__device__ float g_agg[N_NODES*HDIM];        // zero at load; k_post re-zeroes after read
__device__ float g_W2p[L_LAYERS*HDIM*JW + 2*JW];  // +2*JW pad for depth-2 prefetch overread
__device__ int   g_deg_col[N_NODES];         // zero at load; k_setup re-zeroes after read
__device__ float g_inv_deg[N_NODES];
__device__ int   g_deg_row[N_NODES];         // zero at load; k_scan re-zeroes after read
__device__ int   g_row_ptr[N_NODES+1];
__device__ int   g_cursor[N_NODES];
__device__ int   g_se_row[E_EDGES];
__device__ int   g_se_col[E_EDGES];
__device__ float g_musum[HDIM];              // zeroed by k_bnstats after read
__device__ float g_sqsum[HDIM];
__device__ float g_mu[HDIM];
__device__ float g_scale[HDIM];
__device__ float g_gsum[G_GRAPHS*HDIM];      // zeroed by k_cls after read
__device__ unsigned int g_gmaxe[G_GRAPHS*HDIM];
__device__ int   g_gcnt[G_GRAPHS];

// monotone float<->uint encoding for atomicMax on floats; 0u is below all encodings
__device__ __forceinline__ unsigned int fenc(float f){
    int i = __float_as_int(f);
    return (i >= 0) ? ((unsigned int)i | 0x80000000u) : (unsigned int)(~i);
}
__device__ __forceinline__ float fdec(unsigned int u){
    int i = (u & 0x80000000u) ? (int)(u & 0x7FFFFFFFu) : ~(int)u;
    return __int_as_float(i);
}

// ---------------- setup kernels ----------------
__global__ void k_deg(const int* __restrict__ ei){
    int i = blockIdx.x*blockDim.x + threadIdx.x;
    if (i >= E_EDGES) return;
    atomicAdd(&g_deg_row[ei[i]], 1);
    atomicAdd(&g_deg_col[ei[E_EDGES + i]], 1);
}

// single-block warp-shuffle scan over g_deg_row -> g_row_ptr / g_cursor (zeroes deg_row)
__global__ void k_scan(){
    __shared__ int wsum[32];
    __shared__ int s_carry;
    int tid = threadIdx.x, lane = tid & 31, wid = tid >> 5;
    if (tid == 0) s_carry = 0;
    __syncthreads();
    for (int base = 0; base < N_NODES; base += 1024){
        int idx = base + tid;
        int v = 0;
        if (idx < N_NODES){ v = g_deg_row[idx]; g_deg_row[idx] = 0; }
        int inc = v;
        #pragma unroll
        for (int off = 1; off < 32; off <<= 1){
            int t = __shfl_up_sync(0xffffffffu, inc, off);
            if (lane >= off) inc += t;
        }
        if (lane == 31) wsum[wid] = inc;
        __syncthreads();
        if (wid == 0){
            int s = wsum[lane];
            #pragma unroll
            for (int off = 1; off < 32; off <<= 1){
                int t = __shfl_up_sync(0xffffffffu, s, off);
                if (lane >= off) s += t;
            }
            wsum[lane] = s;
        }
        __syncthreads();
        int woff = (wid > 0) ? wsum[wid-1] : 0;
        int excl = s_carry + woff + inc - v;
        if (idx < N_NODES){ g_row_ptr[idx] = excl; g_cursor[idx] = excl; }
        int tot = wsum[31];
        __syncthreads();
        if (tid == 0) s_carry += tot;
        __syncthreads();
    }
    if (tid == 0) g_row_ptr[N_NODES] = s_carry;
}

// fused: fill CSR + permute W2||b2 + inv_deg(+zero deg_col) + embedding GEMM
#define SB_FILL 235
#define SB_PERM 1584
#define SB_INV  79
#define SB_EMB  5000
#define SB_TOTAL (SB_FILL + SB_PERM + SB_INV + SB_EMB)
__global__ void k_setup(const int* __restrict__ ei,
                        const float* __restrict__ eW2, const float* __restrict__ eb2,
                        const float* __restrict__ x, const float* __restrict__ embW,
                        const float* __restrict__ embB){
    int b = blockIdx.x;
    int tid = threadIdx.x;
    if (b < SB_FILL){
        int i = b*256 + tid;
        if (i < E_EDGES){
            int r = ei[i], c = ei[E_EDGES + i];
            int p = atomicAdd(&g_cursor[r], 1);
            g_se_row[p] = r;
            g_se_col[p] = c;
        }
        return;
    }
    b -= SB_FILL;
    if (b < SB_PERM){
        int idx = b*256 + tid;                 // < L*H*JW = 405504 exactly
        int l = idx / (HDIM*JW);
        int rem = idx - l*(HDIM*JW);
        int i = rem / JW;
        int j = rem - i*JW;
        int k = j >> 6, o = j & 63;
        float v;
        if (k < 32) v = eW2[((size_t)(l*32 + k))*4096 + i*64 + o];
        else        v = eb2[(size_t)l*4096 + i*64 + o];
        g_W2p[idx] = v;
        return;
    }
    b -= SB_PERM;
    if (b < SB_INV){
        int i = b*256 + tid;
        if (i < N_NODES){
            int d = g_deg_col[i];
            g_deg_col[i] = 0;                  // ready for next replay
            g_inv_deg[i] = (d > 0) ? (1.0f/(float)d) : 0.0f;
        }
        return;
    }
    b -= SB_INV;
    {   // embedding: 4 nodes per block
        __shared__ float xs[4*F_INPUT];
        int nb = b*4;
        if (tid < 4*F_INPUT) xs[tid] = x[nb*F_INPUT + tid];
        __syncthreads();
        int r = tid >> 6, o = tid & 63;
        float acc = embB[o];
        #pragma unroll
        for (int i = 0; i < F_INPUT; i++)
            acc = fmaf(xs[r*F_INPUT + i], embW[i*HDIM + o], acc);
        g_h[(nb + r)*HDIM + o] = acc;
    }
}

// ---------------- main fused kernel: C-tile GEMM (f32x2, W + h double-buffered) + edge scatter ----------------
__global__ void __launch_bounds__(MAIN_THREADS, 1)
k_main(int l, const float* __restrict__ W1, const float* __restrict__ b1){
    extern __shared__ float sm[];
    float* Cs  = sm;                 // [BM][JW]
    float* hsT = sm + BM*JW;         // [HDIM][BM] transposed h tile
    __shared__ float w1s[32], b1s[32];

    int tid = threadIdx.x;
    int n0  = blockIdx.x * BM;

    if (tid < 32){ w1s[tid] = W1[l*32 + tid]; b1s[tid] = b1[l*32 + tid]; }
    for (int idx = tid; idx < BM*HDIM; idx += MAIN_THREADS){
        int r = idx >> 6, i = idx & 63;
        hsT[i*BM + r] = g_h[(n0 + r)*HDIM + i];
    }
    __syncthreads();

    // GEMM: C[r][j] = sum_i h[r,i]*W2p[i,j]; thread owns col pairs j=2*tid+704*p.
    // Manual unroll-by-2: named double buffers (hA/hB, wbufA/wbufB), no indexed
    // register arrays. W prefetch depth-2 (pad-covered), h prefetch depth-1
    // (row index clamped, no overread).
    const float2* __restrict__ Wp2 =
        reinterpret_cast<const float2*>(g_W2p + (size_t)l*HDIM*JW) + tid;
    unsigned long long acc[3][2][8];
    #pragma unroll
    for (int p = 0; p < 3; p++)
        #pragma unroll
        for (int c = 0; c < 2; c++)
            #pragma unroll
            for (int rp = 0; rp < 8; rp++) acc[p][c][rp] = 0ull;

    float2 wbufA[3], wbufB[3];
    #pragma unroll
    for (int p = 0; p < 3; p++){
        wbufA[p] = Wp2[p*MAIN_THREADS];
        wbufB[p] = Wp2[(JW/2) + p*MAIN_THREADS];
    }
    unsigned long long hA[8], hB[8];
    {
        const unsigned long long* h0 = reinterpret_cast<const unsigned long long*>(hsT);
        #pragma unroll
        for (int rp = 0; rp < 8; rp++) hA[rp] = h0[rp];
    }

    #define FMA2_BLOCK(hreg, wsrc) \
        _Pragma("unroll") \
        for (int p = 0; p < 3; p++){ \
            unsigned long long w2a, w2b; \
            asm("mov.b64 %0, {%1, %1};" : "=l"(w2a) : "f"(wsrc[p].x)); \
            asm("mov.b64 %0, {%1, %1};" : "=l"(w2b) : "f"(wsrc[p].y)); \
            _Pragma("unroll") \
            for (int rp = 0; rp < 8; rp++){ \
                asm("fma.rn.f32x2 %0, %1, %2, %0;" \
                    : "+l"(acc[p][0][rp]) : "l"(hreg[rp]), "l"(w2a)); \
                asm("fma.rn.f32x2 %0, %1, %2, %0;" \
                    : "+l"(acc[p][1][rp]) : "l"(hreg[rp]), "l"(w2b)); \
            } \
        }

    for (int i = 0; i < HDIM; i += 2){
        // ---- even iteration i: compute with (hA, wbufA) ----
        float2 wnA[3];
        #pragma unroll
        for (int p = 0; p < 3; p++)
            wnA[p] = Wp2[(size_t)(i+2)*(JW/2) + p*MAIN_THREADS];   // pad-covered
        {
            const unsigned long long* hn =
                reinterpret_cast<const unsigned long long*>(hsT + (i+1)*BM);
            #pragma unroll
            for (int rp = 0; rp < 8; rp++) hB[rp] = hn[rp];
        }
        FMA2_BLOCK(hA, wbufA)
        #pragma unroll
        for (int p = 0; p < 3; p++) wbufA[p] = wnA[p];

        // ---- odd iteration i+1: compute with (hB, wbufB) ----
        float2 wnB[3];
        #pragma unroll
        for (int p = 0; p < 3; p++)
            wnB[p] = Wp2[(size_t)(i+3)*(JW/2) + p*MAIN_THREADS];   // pad-covered
        {
            int nr = (i+2 < HDIM) ? (i+2) : 0;                     // clamped, in-bounds
            const unsigned long long* hn =
                reinterpret_cast<const unsigned long long*>(hsT + nr*BM);
            #pragma unroll
            for (int rp = 0; rp < 8; rp++) hA[rp] = hn[rp];
        }
        FMA2_BLOCK(hB, wbufB)
        #pragma unroll
        for (int p = 0; p < 3; p++) wbufB[p] = wnB[p];
    }
    #undef FMA2_BLOCK

    #pragma unroll
    for (int p = 0; p < 3; p++){
        int j = 2*tid + 704*p;
        #pragma unroll
        for (int rp = 0; rp < 8; rp++){
            float l0, h0, l1, h1;
            asm("mov.b64 {%0, %1}, %2;" : "=f"(l0), "=f"(h0) : "l"(acc[p][0][rp]));
            asm("mov.b64 {%0, %1}, %2;" : "=f"(l1), "=f"(h1) : "l"(acc[p][1][rp]));
            *reinterpret_cast<float2*>(&Cs[(2*rp  )*JW + j]) = make_float2(l0, l1);
            *reinterpret_cast<float2*>(&Cs[(2*rp+1)*JW + j]) = make_float2(h0, h1);
        }
    }
    __syncthreads();

    // epilogue: per edge, distance + hid + msg = hid_ext . C[row], scatter to agg[col]
    int wid = tid >> 5, lane = tid & 31;
    int es = g_row_ptr[n0], ee = g_row_ptr[n0 + BM];
    for (int e = es + wid; e < ee; e += NWARPS){
        int r = g_se_row[e] - n0;
        int c = g_se_col[e];
        float dx = hsT[0*BM + r] - __ldg(&g_h[c*HDIM + 0]);
        float dy = hsT[1*BM + r] - __ldg(&g_h[c*HDIM + 1]);
        float dz = hsT[2*BM + r] - __ldg(&g_h[c*HDIM + 2]);
        float dd = sqrtf(dx*dx + dy*dy + dz*dz);
        const float* Cr = Cs + r*JW;
        float m0 = Cr[32*64 + lane];        // bias slot (hid=1)
        float m1 = Cr[32*64 + 32 + lane];
        #pragma unroll
        for (int k = 0; k < 32; k++){
            float hk = fmaxf(fmaf(dd, w1s[k], b1s[k]), 0.f);
            m0 = fmaf(hk, Cr[k*64 + lane],      m0);
            m1 = fmaf(hk, Cr[k*64 + 32 + lane], m1);
        }
        atomicAdd(&g_agg[c*HDIM + lane],      m0);
        atomicAdd(&g_agg[c*HDIM + 32 + lane], m1);
    }
}

// out = agg*inv_deg + h@self_W + self_b ; zero agg; fp32 BN stat atomics
__global__ void k_post(int l, const float* __restrict__ sW, const float* __restrict__ sb){
    __shared__ float hsm[4*HDIM];
    __shared__ float red[256];
    __shared__ float red2[256];
    int tid = threadIdx.x;
    int nb = blockIdx.x*4;
    hsm[tid] = g_h[nb*HDIM + tid];
    __syncthreads();
    int r = tid >> 6, o = tid & 63;
    int n = nb + r;
    float a = g_agg[n*HDIM + o];
    g_agg[n*HDIM + o] = 0.f;                 // ready for next layer / next replay
    float acc = a*g_inv_deg[n] + sb[l*HDIM + o];
    const float* W = sW + (size_t)l*HDIM*HDIM;
    #pragma unroll 16
    for (int i = 0; i < HDIM; i++)
        acc = fmaf(hsm[r*HDIM + i], W[i*HDIM + o], acc);
    g_out[n*HDIM + o] = acc;
    red[tid] = acc; red2[tid] = acc*acc;
    __syncthreads();
    if (tid < 64){
        float s  = red [tid] + red [tid+64] + red [tid+128] + red [tid+192];
        float s2 = red2[tid] + red2[tid+64] + red2[tid+128] + red2[tid+192];
        atomicAdd(&g_musum[tid], s);
        atomicAdd(&g_sqsum[tid], s2);
    }
}

__global__ void k_bnstats(int l, const float* __restrict__ gamma){
    int o = threadIdx.x;
    if (o >= HDIM) return;
    float mu  = g_musum[o] * (1.0f/(float)N_NODES);
    float ex2 = g_sqsum[o] * (1.0f/(float)N_NODES);
    float var = ex2 - mu*mu;
    g_mu[o] = mu;
    g_scale[o] = gamma[l*HDIM + o] * rsqrtf(var + EPSV);
    g_musum[o] = 0.f;                        // ready for next layer
    g_sqsum[o] = 0.f;
}

// BN apply + relu + skip; for last layer also graph pooling atomics
__global__ void k_bnapply(int l, const float* __restrict__ beta,
                          const int* __restrict__ batch, int do_pool){
    int idx = blockIdx.x*blockDim.x + threadIdx.x;
    if (idx >= N_NODES*HDIM) return;
    int o = idx & 63;
    float v = (g_out[idx] - g_mu[o])*g_scale[o] + beta[l*HDIM + o];
    float hnew = g_h[idx] + fmaxf(v, 0.f);
    g_h[idx] = hnew;
    if (do_pool){
        int n = idx >> 6;
        int g = batch[n];
        atomicAdd(&g_gsum[g*HDIM + o], hnew);
        atomicMax(&g_gmaxe[g*HDIM + o], fenc(hnew));
        if (o == 0) atomicAdd(&g_gcnt[g], 1);
    }
}

// ---------------- classifier (also zeroes pooling scratch after read) ----------------
__global__ void k_cls(const float* __restrict__ W1, const float* __restrict__ b1,
                      const float* __restrict__ W2, const float* __restrict__ b2,
                      float* __restrict__ out){
    __shared__ float gv[2*HDIM];
    __shared__ float h1[HDIM];
    __shared__ float partials[2];
    int g = blockIdx.x, tid = threadIdx.x;
    int cnt = g_gcnt[g];
    if (tid < HDIM){
        gv[tid] = g_gsum[g*HDIM + tid] / fmaxf((float)cnt, 1.f);
    } else {
        int o = tid - HDIM;
        gv[tid] = (cnt > 0) ? fdec(g_gmaxe[g*HDIM + o]) : 0.f;
    }
    __syncthreads();
    // scratch fully read -> zero for next replay
    if (tid < HDIM) g_gsum[g*HDIM + tid] = 0.f;
    else            g_gmaxe[g*HDIM + (tid - HDIM)] = 0u;
    if (tid == 0)   g_gcnt[g] = 0;
    if (tid < HDIM){
        float a = b1[tid];
        #pragma unroll 8
        for (int i = 0; i < 2*HDIM; i++)
            a = fmaf(gv[i], W1[i*HDIM + tid], a);
        h1[tid] = fmaxf(a, 0.f);
    }
    __syncthreads();
    float p = 0.f;
    if (tid < HDIM){
        p = h1[tid]*W2[tid];
        #pragma unroll
        for (int off = 16; off > 0; off >>= 1)
            p += __shfl_down_sync(0xffffffffu, p, off);
        if ((tid & 31) == 0) partials[tid >> 5] = p;
    }
    __syncthreads();
    if (tid == 0){
        float t = partials[0] + partials[1] + b2[0];
        out[g] = 1.f/(1.f + expf(-t));
    }
}

// ---------------- launcher ----------------
extern "C" void kernel_launch(void* const* d_in, const int* in_sizes, int n_in,
                              void* d_out, int out_size){
    const float* x        = (const float*)d_in[0];
    const int*   ei       = (const int*)  d_in[1];
    const int*   batch    = (const int*)  d_in[2];
    const float* emb_W    = (const float*)d_in[3];
    const float* emb_b    = (const float*)d_in[4];
    const float* edge_W1  = (const float*)d_in[5];
    const float* edge_b1  = (const float*)d_in[6];
    const float* edge_W2  = (const float*)d_in[7];
    const float* edge_b2  = (const float*)d_in[8];
    const float* self_W   = (const float*)d_in[9];
    const float* self_b   = (const float*)d_in[10];
    const float* bn_gamma = (const float*)d_in[11];
    const float* bn_beta  = (const float*)d_in[12];
    const float* cls_W1   = (const float*)d_in[13];
    const float* cls_b1   = (const float*)d_in[14];
    const float* cls_W2   = (const float*)d_in[15];
    const float* cls_b2   = (const float*)d_in[16];
    float* out = (float*)d_out;

    const int smem_main = (BM*JW + HDIM*BM)*(int)sizeof(float); // 139264 B
    cudaFuncSetAttribute(k_main, cudaFuncAttributeMaxDynamicSharedMemorySize, smem_main);

    const int TB = 256;
    const int gE   = (E_EDGES + TB - 1)/TB;          // 235
    const int gNH  = (N_NODES*HDIM + TB - 1)/TB;     // 5000
    const int gMain= N_NODES/BM;                     // 1250

    k_deg<<<gE, TB>>>(ei);
    k_scan<<<1, 1024>>>();
    k_setup<<<SB_TOTAL, TB>>>(ei, edge_W2, edge_b2, x, emb_W, emb_b);

    for (int l = 0; l < L_LAYERS; l++){
        k_main<<<gMain, MAIN_THREADS, smem_main>>>(l, edge_W1, edge_b1);
        k_post<<<N_NODES/4, TB>>>(l, self_W, self_b);
        k_bnstats<<<1, 64>>>(l, bn_gamma);
        k_bnapply<<<gNH, TB>>>(l, bn_beta, batch, (l == L_LAYERS-1) ? 1 : 0);
    }

    k_cls<<<G_GRAPHS, 128>>>(cls_W1, cls_b1, cls_W2, cls_b2, out);
}